// round 17
// baseline (speedup 1.0000x reference)
#include <cuda_runtime.h>
#include <cuda_fp16.h>
#include <cstdint>

// AttentionalPropagation R17: [B,L,C] intermediate layout + msg double-buffer.
//   K0:  x[B,C,L] fp32 -> xT[B,L,C] fp16. Writes now 128B runs @1KB stride
//        (dense) instead of @64KB.
//   K12: R16 core (ldmatrix, fp16 m16n8k16, resident swizzled planes,
//        3 CTAs/SM) with [B,L,C] addressing and double-buffered msg planes
//        (one barrier per pass-2 chunk instead of two).
//   K3:  oT[B,L,C] fp16 -> out[B,C,L] fp32. Reads now 128B runs @1KB stride.
// mma / softmax / P->A packing / swizzle verbatim (locked, rel_err 2.077e-4).

namespace {

constexpr int kB  = 64;
constexpr int kC  = 512;
constexpr int kL  = 4096;
constexpr int kBC = kB * kC;
constexpr int CCH = 32;
constexpr int NCH = kC / CCH;        // 16

constexpr int PLANE_B = 4096;        // bytes per chunk plane (64 b x 64B)
constexpr int MSGP    = 40;          // msg pitch (halves)
constexpr int MSG_H   = kB * MSGP;   // halves per msg plane (5120B)
constexpr int OFF_MSG = NCH * PLANE_B;                  // 65536
constexpr int SMEM_K12 = OFF_MSG + 2 * MSG_H * 2;       // 75776 B -> 3 CTAs/SM

__device__ __half xT_g[(size_t)kL * kBC];           // 256 MB [B][L][C] fp16
__device__ __half oT_g[(size_t)kL * kBC];           // 256 MB [B][L][C] fp16

__device__ __forceinline__ void mma_f16(float d[4],
                                        uint32_t a0, uint32_t a1, uint32_t a2, uint32_t a3,
                                        uint32_t b0, uint32_t b1) {
    asm volatile(
        "mma.sync.aligned.m16n8k16.row.col.f32.f16.f16.f32 "
        "{%0,%1,%2,%3}, {%4,%5,%6,%7}, {%8,%9}, {%0,%1,%2,%3};"
        : "+f"(d[0]), "+f"(d[1]), "+f"(d[2]), "+f"(d[3])
        : "r"(a0), "r"(a1), "r"(a2), "r"(a3), "r"(b0), "r"(b1));
}

__device__ __forceinline__ void ldsm_x4(uint32_t& r0, uint32_t& r1,
                                        uint32_t& r2, uint32_t& r3, uint32_t addr) {
    asm volatile("ldmatrix.sync.aligned.m8n8.x4.shared.b16 {%0,%1,%2,%3}, [%4];"
                 : "=r"(r0), "=r"(r1), "=r"(r2), "=r"(r3) : "r"(addr));
}
__device__ __forceinline__ void ldsm_x4_t(uint32_t& r0, uint32_t& r1,
                                          uint32_t& r2, uint32_t& r3, uint32_t addr) {
    asm volatile("ldmatrix.sync.aligned.m8n8.x4.trans.shared.b16 {%0,%1,%2,%3}, [%4];"
                 : "=r"(r0), "=r"(r1), "=r"(r2), "=r"(r3) : "r"(addr));
}

__device__ __forceinline__ void cp16(uint32_t dst, const void* src) {
    asm volatile("cp.async.ca.shared.global [%0], [%1], 16;" :: "r"(dst), "l"(src));
}
__device__ __forceinline__ void cp_commit() {
    asm volatile("cp.async.commit_group;" ::: "memory");
}
template <int N>
__device__ __forceinline__ void cp_wait() {
    asm volatile("cp.async.wait_group %0;" :: "n"(N) : "memory");
}
__device__ __forceinline__ void cp_wait_n(int n) {   // constant-folded call sites
    switch (n) {
        case 0:  cp_wait<0>();  break;  case 1:  cp_wait<1>();  break;
        case 2:  cp_wait<2>();  break;  case 3:  cp_wait<3>();  break;
        case 4:  cp_wait<4>();  break;  case 5:  cp_wait<5>();  break;
        case 6:  cp_wait<6>();  break;  case 7:  cp_wait<7>();  break;
        case 8:  cp_wait<8>();  break;  case 9:  cp_wait<9>();  break;
        case 10: cp_wait<10>(); break;  case 11: cp_wait<11>(); break;
        case 12: cp_wait<12>(); break;  case 13: cp_wait<13>(); break;
        case 14: cp_wait<14>(); break;  default: cp_wait<15>(); break;
    }
}

__device__ __forceinline__ uint32_t h2u(half2 h) {
    return *reinterpret_cast<uint32_t*>(&h);
}

// ---- K0: x[B,C,L] fp32 -> xT[B,L,C] fp16 -----------------------------------
// Tile: one b, 64 c, 128 l. Loads: 64B runs per c-row. Writes: per l, 64 c
// halves = 128B contiguous @1KB stride (dense).
__global__ void __launch_bounds__(256)
k0_transpose(const float* __restrict__ x) {
    const int C0  = blockIdx.x * 128;       // l block
    const int R0  = blockIdx.y * 64;        // bc block (single b)
    const int b   = R0 >> 9;
    const int c0  = R0 & 511;
    const int t   = threadIdx.x;
    const int bc8 = t & 7;                  // c sub-block of 8
    const int lb  = t >> 3;                 // l group of 4

    float4 r[8];
    #pragma unroll
    for (int i = 0; i < 8; i++)
        r[i] = *(const float4*)(x + (size_t)(R0 + 8 * bc8 + i) * kL + C0 + 4 * lb);

    #pragma unroll
    for (int k = 0; k < 4; k++) {
        float v[8];
        #pragma unroll
        for (int i = 0; i < 8; i++)
            v[i] = k == 0 ? r[i].x : k == 1 ? r[i].y : k == 2 ? r[i].z : r[i].w;
        uint4 pk;
        pk.x = h2u(__floats2half2_rn(v[0], v[1]));
        pk.y = h2u(__floats2half2_rn(v[2], v[3]));
        pk.z = h2u(__floats2half2_rn(v[4], v[5]));
        pk.w = h2u(__floats2half2_rn(v[6], v[7]));
        *reinterpret_cast<uint4*>(
            xT_g + ((size_t)b * kL + (C0 + 4 * lb + k)) * kC + c0 + 8 * bc8) = pk;
    }
}

// ---- K3: oT[B,L,C] fp16 -> out[B,C,L] fp32 ---------------------------------
__global__ void __launch_bounds__(256)
k3_transpose(float* __restrict__ out) {
    const int C0  = blockIdx.x * 128;       // l block
    const int R0  = blockIdx.y * 64;        // bc block (single b)
    const int b   = R0 >> 9;
    const int c0  = R0 & 511;
    const int t   = threadIdx.x;
    const int bc8 = t & 7;
    const int lb  = t >> 3;

    uint4 rv[4];
    #pragma unroll
    for (int k = 0; k < 4; k++)
        rv[k] = *reinterpret_cast<const uint4*>(
            oT_g + ((size_t)b * kL + (C0 + 4 * lb + k)) * kC + c0 + 8 * bc8);

    #pragma unroll
    for (int i = 0; i < 8; i++) {
        float o[4];
        #pragma unroll
        for (int k = 0; k < 4; k++) {
            const uint32_t w = i < 2 ? rv[k].x : i < 4 ? rv[k].y
                             : i < 6 ? rv[k].z : rv[k].w;
            const float2 f2 = __half22float2(*reinterpret_cast<const half2*>(&w));
            o[k] = (i & 1) ? f2.y : f2.x;
        }
        *(float4*)(out + (size_t)(R0 + 8 * bc8 + i) * kL + C0 + 4 * lb) =
            make_float4(o[0], o[1], o[2], o[3]);
    }
}

// ====================== K12: fused scores+softmax+apply =====================
__global__ void __launch_bounds__(128)
k12_fused() {
    extern __shared__ __align__(16) char smraw[];
    __half* msg0 = reinterpret_cast<__half*>(smraw + OFF_MSG);

    const int t = threadIdx.x, lane = t & 31;
    const int strip = t >> 5;              // warp = 16-row strip of S
    const int l = blockIdx.x;
    const int r0 = lane >> 2, q4 = lane & 3;
    const uint32_t smb = (uint32_t)__cvta_generic_to_shared(smraw);

    // ---- stage all 16 chunk planes (2 cp16/thread/chunk, 16 groups) --------
    {
        const int b = t >> 1, h = t & 1;
        const int bx = (b >> 1) & 3;                       // swizzle key
        const __half* src0 = xT_g + ((size_t)b * kL + l) * kC;
        #pragma unroll
        for (int ch = 0; ch < NCH; ch++) {
            #pragma unroll
            for (int i = 0; i < 2; i++) {
                const int g = 2 * h + i;
                cp16(smb + (uint32_t)(ch * PLANE_B + b * 64 + ((g ^ bx) << 4)),
                     src0 + ch * CCH + g * 8);
            }
            cp_commit();
        }
    }

    // ---- lane-invariant ldmatrix address components -------------------------
    const int mat = lane >> 3, l8 = lane & 7;
    const int a_row = strip * 16 + ((mat & 1) << 3) + l8;
    const int a_gs  = mat >> 1;
    const int a_xr  = (a_row >> 1) & 3;
    const int b_nb  = ((mat >> 1) << 3) + l8;
    const int b_gs  = mat & 1;
    const int t_kb  = ((mat & 1) << 3) + l8;
    const int t_gs  = mat >> 1;

    float acc[8][4];
    #pragma unroll
    for (int j = 0; j < 8; j++)
        #pragma unroll
        for (int i = 0; i < 4; i++) acc[j][i] = 0.0f;

    // -------- Pass 1: S = q q^T, progressive over arriving planes ------------
    #pragma unroll 1
    for (int ch = 0; ch < NCH; ch++) {
        cp_wait_n(NCH - 1 - ch);
        __syncthreads();                   // plane ch visible to all warps
        const uint32_t pl = smb + (uint32_t)(ch * PLANE_B);
        #pragma unroll
        for (int sk = 0; sk < 2; sk++) {
            uint32_t a0, a1, a2, a3;
            ldsm_x4(a0, a1, a2, a3,
                    pl + a_row * 64 + (((2 * sk + a_gs) ^ a_xr) << 4));
            #pragma unroll
            for (int jj = 0; jj < 4; jj++) {
                const int nrow = 16 * jj + b_nb;
                uint32_t b00, b01, b10, b11;
                ldsm_x4(b00, b01, b10, b11,
                        pl + nrow * 64 +
                        (((2 * sk + b_gs) ^ ((nrow >> 1) & 3)) << 4));
                mma_f16(acc[2 * jj],     a0, a1, a2, a3, b00, b01);
                mma_f16(acc[2 * jj + 1], a0, a1, a2, a3, b10, b11);
            }
        }
    }

    // -------- Softmax (verbatim) ---------------------------------------------
    {
        const float isc = 0.044194173824159216f;   // 1/sqrt(512)
        #pragma unroll
        for (int hh = 0; hh < 2; hh++) {
            float mx = -1e30f;
            #pragma unroll
            for (int j = 0; j < 8; j++) {
                acc[j][2 * hh]     *= isc;
                acc[j][2 * hh + 1] *= isc;
                mx = fmaxf(mx, fmaxf(acc[j][2 * hh], acc[j][2 * hh + 1]));
            }
            mx = fmaxf(mx, __shfl_xor_sync(0xffffffffu, mx, 1));
            mx = fmaxf(mx, __shfl_xor_sync(0xffffffffu, mx, 2));
            float ssum = 0.0f;
            #pragma unroll
            for (int j = 0; j < 8; j++) {
                const float e0 = __expf(acc[j][2 * hh] - mx);
                const float e1 = __expf(acc[j][2 * hh + 1] - mx);
                acc[j][2 * hh] = e0; acc[j][2 * hh + 1] = e1;
                ssum += e0 + e1;
            }
            ssum += __shfl_xor_sync(0xffffffffu, ssum, 1);
            ssum += __shfl_xor_sync(0xffffffffu, ssum, 2);
            const float inv = 1.0f / ssum;
            #pragma unroll
            for (int j = 0; j < 8; j++) {
                acc[j][2 * hh] *= inv; acc[j][2 * hh + 1] *= inv;
            }
        }
    }

    // -------- P -> f16 A-frags (in-lane packing, verified) ------------------
    uint32_t ah[4][4];
    #pragma unroll
    for (int sk2 = 0; sk2 < 4; sk2++) {
        ah[sk2][0] = h2u(__floats2half2_rn(acc[2*sk2][0],   acc[2*sk2][1]));
        ah[sk2][1] = h2u(__floats2half2_rn(acc[2*sk2][2],   acc[2*sk2][3]));
        ah[sk2][2] = h2u(__floats2half2_rn(acc[2*sk2+1][0], acc[2*sk2+1][1]));
        ah[sk2][3] = h2u(__floats2half2_rn(acc[2*sk2+1][2], acc[2*sk2+1][3]));
    }

    // -------- Pass 2: msg = P q via ldmatrix.trans; double-buffered msg ------
    #pragma unroll 1
    for (int ch = 0; ch < NCH; ch++) {
        const uint32_t pl = smb + (uint32_t)(ch * PLANE_B);
        __half* msg = msg0 + (ch & 1) * MSG_H;

        float macc[4][4];
        #pragma unroll
        for (int j2 = 0; j2 < 4; j2++)
            #pragma unroll
            for (int i = 0; i < 4; i++) macc[j2][i] = 0.0f;

        #pragma unroll
        for (int sk2 = 0; sk2 < 4; sk2++) {       // k over m = 64
            const int krow = 16 * sk2 + t_kb;
            const int kxr  = (krow >> 1) & 3;
            #pragma unroll
            for (int jj2 = 0; jj2 < 2; jj2++) {   // c-granule pairs
                uint32_t c00, c01, c10, c11;
                ldsm_x4_t(c00, c01, c10, c11,
                          pl + krow * 64 + (((2 * jj2 + t_gs) ^ kxr) << 4));
                mma_f16(macc[2 * jj2],     ah[sk2][0], ah[sk2][1],
                        ah[sk2][2], ah[sk2][3], c00, c01);
                mma_f16(macc[2 * jj2 + 1], ah[sk2][0], ah[sk2][1],
                        ah[sk2][2], ah[sk2][3], c10, c11);
            }
        }

        // msg fragments -> fp16 smem [n][c] pitch MSGP halves.
        #pragma unroll
        for (int j2 = 0; j2 < 4; j2++) {
            __half* mp = msg + (strip * 16 + r0) * MSGP + 8 * j2 + 2 * q4;
            *reinterpret_cast<half2*>(mp) =
                __floats2half2_rn(macc[j2][0], macc[j2][1]);
            *reinterpret_cast<half2*>(mp + 8 * MSGP) =
                __floats2half2_rn(macc[j2][2], macc[j2][3]);
        }
        __syncthreads();                   // msg visible (no drain barrier:
                                           // next chunk uses the other plane)

        // Epilogue: oT = x (from resident plane) + msg, fp16, 32B stores.
        {
            const int b = t >> 1, h = t & 1;
            const int bx = (b >> 1) & 3;
            const __half* plh = reinterpret_cast<const __half*>(smraw)
                              + ch * (PLANE_B / 2) + b * 32;
            uint4 xv[2];
            #pragma unroll
            for (int i = 0; i < 2; i++) {
                const int g = 2 * h + i;
                xv[i] = *reinterpret_cast<const uint4*>(plh + ((g ^ bx) << 3));
            }
            const uint4 mv0 = reinterpret_cast<const uint4*>(msg + b * MSGP + h * 16)[0];
            const uint4 mv1 = reinterpret_cast<const uint4*>(msg + b * MSGP + h * 16)[1];
            const uint32_t xw[8] = {xv[0].x, xv[0].y, xv[0].z, xv[0].w,
                                    xv[1].x, xv[1].y, xv[1].z, xv[1].w};
            const uint32_t mw[8] = {mv0.x, mv0.y, mv0.z, mv0.w,
                                    mv1.x, mv1.y, mv1.z, mv1.w};
            uint32_t ow[8];
            #pragma unroll
            for (int k = 0; k < 8; k++) {
                const half2 xh = *reinterpret_cast<const half2*>(&xw[k]);
                const half2 mh = *reinterpret_cast<const half2*>(&mw[k]);
                ow[k] = h2u(__hadd2(xh, mh));
            }
            __half* op = oT_g + ((size_t)b * kL + l) * kC + ch * CCH + h * 16;
            reinterpret_cast<uint4*>(op)[0] = make_uint4(ow[0], ow[1], ow[2], ow[3]);
            reinterpret_cast<uint4*>(op)[1] = make_uint4(ow[4], ow[5], ow[6], ow[7]);
        }
    }
}

}  // namespace

extern "C" void kernel_launch(void* const* d_in, const int* in_sizes, int n_in,
                              void* d_out, int out_size) {
    (void)in_sizes; (void)n_in; (void)out_size;
    const float* x = (const float*)d_in[0];
    float* out     = (float*)d_out;

    cudaFuncSetAttribute(k12_fused,
                         cudaFuncAttributeMaxDynamicSharedMemorySize, SMEM_K12);

    dim3 gt(kL / 128, kBC / 64);       // 32 x 512
    k0_transpose<<<gt, 256>>>(x);
    k12_fused<<<kL, 128, SMEM_K12>>>();
    k3_transpose<<<gt, 256>>>(out);
}